// round 9
// baseline (speedup 1.0000x reference)
#include <cuda_runtime.h>
#include <math.h>

#define NN 10000
#define NE 200000
#define HC 320          // HEADS*CONV_DIM = 5*64
#define CD 64
#define ED 16

typedef unsigned long long u64;

// ---------------- device scratch (no allocations allowed) ----------------
__device__ __align__(16) float g_xl[NN * HC];         // per-layer node features [N,320]
__device__ __align__(16) float g_h1[NN * CD];
__device__ __align__(16) float g_h2[NN * CD];
__device__ __align__(16) float g_ea2[(NE + 32) * ED]; // edge_attr permuted to CSR order (+pad)
__device__ int g_srcs[NE + 32];                       // src node per CSR slot (+pad)
__device__ int g_off[NN + 1];                         // CSR offsets (by dst)
__device__ int g_cnt[NN];

// ---------------- f32x2 helpers ----------------
__device__ __forceinline__ u64 pk2(float lo, float hi) {
    u64 r;
    asm("mov.b64 %0, {%1, %2};" : "=l"(r) : "f"(lo), "f"(hi));
    return r;
}
__device__ __forceinline__ void upk2(u64 v, float& lo, float& hi) {
    asm("mov.b64 {%0, %1}, %2;" : "=f"(lo), "=f"(hi) : "l"(v));
}
__device__ __forceinline__ u64 ffma2(u64 a, u64 b, u64 c) {
    u64 d;
    asm("fma.rn.f32x2 %0, %1, %2, %3;" : "=l"(d) : "l"(a), "l"(b), "l"(c));
    return d;
}
__device__ __forceinline__ u64 fadd2(u64 a, u64 b) {
    u64 d;
    asm("add.rn.f32x2 %0, %1, %2;" : "=l"(d) : "l"(a), "l"(b));
    return d;
}
__device__ __forceinline__ u64 fmul2(u64 a, u64 b) {
    u64 d;
    asm("mul.rn.f32x2 %0, %1, %2;" : "=l"(d) : "l"(a), "l"(b));
    return d;
}
__device__ __forceinline__ float ex2f(float x) {
    float r;
    asm("ex2.approx.f32 %0, %1;" : "=f"(r) : "f"(x));
    return r;
}

// ---------------- preprocessing ----------------
// One block: histogram degrees in smem, scan, write offsets + zero counters.
__global__ void __launch_bounds__(1024) k_degscan(const int* __restrict__ ei) {
    __shared__ int hist[NN];
    __shared__ int sums[1024];
    const int t = threadIdx.x;
    for (int i = t; i < NN; i += 1024) hist[i] = 0;
    __syncthreads();
    for (int e = t; e < NE; e += 1024) atomicAdd(&hist[ei[NE + e]], 1);
    __syncthreads();
    const int per = 10;  // 1024*10 >= 10000
    int base = t * per;
    int s = 0;
#pragma unroll
    for (int i = 0; i < per; i++) {
        int idx = base + i;
        if (idx < NN) s += hist[idx];
    }
    sums[t] = s;
    __syncthreads();
    for (int off = 1; off < 1024; off <<= 1) {
        int v = 0;
        if (t >= off) v = sums[t - off];
        __syncthreads();
        sums[t] += v;
        __syncthreads();
    }
    int run = (t == 0) ? 0 : sums[t - 1];
#pragma unroll
    for (int i = 0; i < per; i++) {
        int idx = base + i;
        if (idx < NN) {
            g_off[idx] = run;
            g_cnt[idx] = 0;
            run += hist[idx];
        }
    }
    if (t == 0) g_off[NN] = NE;
}

// Scatter edges into CSR order: src ids + permuted edge_attr rows in one pass.
__global__ void k_scatter2(const int* __restrict__ ei, const float* __restrict__ ea) {
    int e = blockIdx.x * blockDim.x + threadIdx.x;
    if (e >= NE) return;
    int d = ei[NE + e];
    int pos = g_off[d] + atomicAdd(&g_cnt[d], 1);
    g_srcs[pos] = ei[e];
    const float4* r = (const float4*)(ea + (size_t)e * ED);
    float4 v0 = r[0], v1 = r[1], v2 = r[2], v3 = r[3];
    float4* w = (float4*)(g_ea2 + (size_t)pos * ED);
    w[0] = v0; w[1] = v1; w[2] = v2; w[3] = v3;
}

// ---------------- GEMM: C[M,320] = A[M,K] @ W[K,320] + bias ----------------
#define BM 128
#define BN 64
#define BK 16

__global__ void __launch_bounds__(256) k_gemm(
    const float* __restrict__ A, const float* __restrict__ W,
    const float* __restrict__ bias, float* __restrict__ C, int K)
{
    __shared__ float At[BK][BM + 4];
    __shared__ float Bs[BK][BN];
    const int tid = threadIdx.x;
    const int row0 = blockIdx.x * BM;
    const int col0 = blockIdx.y * BN;
    const int tx = tid & 15;
    const int ty = tid >> 4;

    float acc[8][4];
#pragma unroll
    for (int i = 0; i < 8; i++)
#pragma unroll
        for (int j = 0; j < 4; j++) acc[i][j] = 0.f;

    for (int k0 = 0; k0 < K; k0 += BK) {
#pragma unroll
        for (int i = 0; i < 2; i++) {
            int f = tid * 2 + i;
            int r = f >> 2;
            int kc = (f & 3) << 2;
            int gr = row0 + r;
            float4 v = make_float4(0.f, 0.f, 0.f, 0.f);
            if (gr < NN) v = *(const float4*)(A + (size_t)gr * K + k0 + kc);
            At[kc + 0][r] = v.x;
            At[kc + 1][r] = v.y;
            At[kc + 2][r] = v.z;
            At[kc + 3][r] = v.w;
        }
        {
            int k = tid >> 4;
            int c = (tid & 15) << 2;
            *(float4*)&Bs[k][c] = *(const float4*)(W + (size_t)(k0 + k) * HC + col0 + c);
        }
        __syncthreads();
#pragma unroll
        for (int k = 0; k < BK; k++) {
            float a[8], b[4];
            *(float4*)&a[0] = *(const float4*)&At[k][ty * 8];
            *(float4*)&a[4] = *(const float4*)&At[k][ty * 8 + 4];
            *(float4*)&b[0] = *(const float4*)&Bs[k][tx * 4];
#pragma unroll
            for (int i = 0; i < 8; i++)
#pragma unroll
                for (int j = 0; j < 4; j++)
                    acc[i][j] = fmaf(a[i], b[j], acc[i][j]);
        }
        __syncthreads();
    }

    float4 bv = *(const float4*)&bias[col0 + tx * 4];
#pragma unroll
    for (int i = 0; i < 8; i++) {
        int gr = row0 + ty * 8 + i;
        if (gr < NN) {
            float4 o;
            o.x = acc[i][0] + bv.x;
            o.y = acc[i][1] + bv.y;
            o.z = acc[i][2] + bv.z;
            o.w = acc[i][3] + bv.w;
            *(float4*)&C[(size_t)gr * HC + col0 + tx * 4] = o;
        }
    }
}

// ---------------- fused GATv2 layer v8 ----------------
// 160 threads = 5 warps = 1 node; warp h owns head h (2 comps/lane, packed f32x2).
// NO smem staging, NO barriers in the edge loop: edge_attr read directly via
// broadcast LDG.128 (CSR-contiguous, L1-hit after first warp); src ids via one
// lane-load per 32-window + register shuffles. Gathers for group g+1 prefetched
// while group g computes (xsum trick frees xs registers early). Virtual self loop.
__global__ void __launch_bounds__(160, 4) k_gat(
    const float* __restrict__ We, const float* __restrict__ att,
    const float* __restrict__ bias, float* __restrict__ out)
{
    const int tid = threadIdx.x;
    const int lane = tid & 31;
    const int h = tid >> 5;
    const int coff = h * 64 + 2 * lane;
    const unsigned FULL = 0xffffffffu;
    const float LOG2E = 1.4426950408889634f;

    const float attx = att[coff] * LOG2E;
    const float atty = att[coff + 1] * LOG2E;
    u64 We2[16];
#pragma unroll
    for (int kk = 0; kk < 8; kk++) {
        We2[kk]     = pk2(We[(2 * kk) * HC + coff],     We[(2 * kk + 1) * HC + coff]);
        We2[kk + 8] = pk2(We[(2 * kk) * HC + coff + 1], We[(2 * kk + 1) * HC + coff + 1]);
    }
    const u64 C02 = pk2(0.2f, 0.2f);

    __shared__ float s_red[5][64];

    const int n = blockIdx.x;
    const u64 xld2 = *(const u64*)(g_xl + (size_t)n * HC + coff);
    const int base0 = g_off[n];
    const int deg = g_off[n + 1] - base0;

    float den = 0.f;
    u64 acc2 = pk2(0.f, 0.f);
    u64 es0 = pk2(0.f, 0.f), es1 = pk2(0.f, 0.f);  // running e_emb sums (self loop)

    for (int base = 0; base < deg; base += 32) {
        const int cnt = min(32, deg - base);

        // src ids for this window: one load per lane (array padded), shuffled out
        const int my_src = g_srcs[base0 + base + lane];

        // preload gathers for group 0
        u64 xs2[8];
#pragma unroll
        for (int j = 0; j < 8; j++) {
            int s = __shfl_sync(FULL, my_src, min(j, cnt - 1));
            xs2[j] = *(const u64*)(g_xl + (size_t)s * HC + coff);
        }

        for (int g0 = 0; g0 < cnt; g0 += 8) {
            const int vcnt = min(8, cnt - g0);

            // consume xs2 immediately; xs registers become free
            u64 xsum[8];
#pragma unroll
            for (int j = 0; j < 8; j++) xsum[j] = fadd2(xs2[j], xld2);

            // prefetch next group's gathers (hidden behind this group's compute)
            if (g0 + 8 < cnt) {
#pragma unroll
                for (int j = 0; j < 8; j++) {
                    int s = __shfl_sync(FULL, my_src, min(g0 + 8 + j, cnt - 1));
                    xs2[j] = *(const u64*)(g_xl + (size_t)s * HC + coff);
                }
            }

            float sc[8];
#pragma unroll
            for (int j = 0; j < 8; j++) {
                if (j < vcnt) {
                    // direct broadcast LDG.128 of the CSR-contiguous edge_attr row
                    const ulonglong2* q = (const ulonglong2*)(
                        g_ea2 + (size_t)(base0 + base + g0 + j) * ED);
                    ulonglong2 q0 = q[0], q1 = q[1], q2 = q[2], q3 = q[3];
                    u64 a0 = pk2(0.f, 0.f), a1 = pk2(0.f, 0.f);
                    a0 = ffma2(q0.x, We2[0], a0);  a1 = ffma2(q0.x, We2[8],  a1);
                    a0 = ffma2(q0.y, We2[1], a0);  a1 = ffma2(q0.y, We2[9],  a1);
                    a0 = ffma2(q1.x, We2[2], a0);  a1 = ffma2(q1.x, We2[10], a1);
                    a0 = ffma2(q1.y, We2[3], a0);  a1 = ffma2(q1.y, We2[11], a1);
                    a0 = ffma2(q2.x, We2[4], a0);  a1 = ffma2(q2.x, We2[12], a1);
                    a0 = ffma2(q2.y, We2[5], a0);  a1 = ffma2(q2.y, We2[13], a1);
                    a0 = ffma2(q3.x, We2[6], a0);  a1 = ffma2(q3.x, We2[14], a1);
                    a0 = ffma2(q3.y, We2[7], a0);  a1 = ffma2(q3.y, We2[15], a1);
                    es0 = fadd2(es0, a0);          // e_emb running sums (self loop)
                    es1 = fadd2(es1, a1);
                    float l0, h0, l1, h1;
                    upk2(a0, l0, h0);
                    upk2(a1, l1, h1);
                    u64 upair = fadd2(pk2(l0 + h0, l1 + h1), xsum[j]);
                    u64 tpair = fmul2(upair, C02);
                    float u0, u1, t0, t1;
                    upk2(upair, u0, u1);
                    upk2(tpair, t0, t1);
                    float lr0 = fmaxf(u0, t0);
                    float lr1 = fmaxf(u1, t1);
                    sc[j] = fmaf(attx, lr0, atty * lr1);
                } else {
                    sc[j] = -1000.f;   // exp2 -> 0
                }
            }

            // 8 pipelined butterflies (identical sums on all lanes)
#pragma unroll
            for (int o = 16; o; o >>= 1) {
#pragma unroll
                for (int j = 0; j < 8; j++)
                    sc[j] += __shfl_xor_sync(FULL, sc[j], o);
            }

            // direct softmax accumulation over (xs + xld)
#pragma unroll
            for (int j = 0; j < 8; j++) {
                float p = ex2f(fminf(sc[j], 100.f));
                den += p;
                acc2 = ffma2(pk2(p, p), xsum[j], acc2);
            }
        }
    }

    // undo the +xld aggregation bias: acc_true = acc - den*xld
    acc2 = ffma2(pk2(-den, -den), xld2, acc2);

    // virtual self loop: e_emb = mean of edge e_embs; x-part = 2*xld
    {
        float inv = (deg > 0) ? (1.f / (float)deg) : 1.f;
        float e0l, e0h, e1l, e1h, xx, xy;
        upk2(es0, e0l, e0h);
        upk2(es1, e1l, e1h);
        upk2(xld2, xx, xy);
        float u0 = fmaf(e0l + e0h, inv, 2.f * xx);
        float u1 = fmaf(e1l + e1h, inv, 2.f * xy);
        float lr0 = fmaxf(u0, 0.2f * u0);
        float lr1 = fmaxf(u1, 0.2f * u1);
        float scl = fmaf(attx, lr0, atty * lr1);
#pragma unroll
        for (int o = 16; o; o >>= 1) scl += __shfl_xor_sync(FULL, scl, o);
        float p = ex2f(fminf(scl, 100.f));
        den += p;
        acc2 = ffma2(pk2(p, p), xld2, acc2);
    }

    float invd = 1.f / den;
    float acc0, acc1;
    upk2(acc2, acc0, acc1);
    s_red[h][2 * lane]     = acc0 * invd;
    s_red[h][2 * lane + 1] = acc1 * invd;
    __syncthreads();

    if (tid < CD) {
        float o = (s_red[0][tid] + s_red[1][tid] + s_red[2][tid] +
                   s_red[3][tid] + s_red[4][tid]) * 0.2f + bias[tid];
        o = (o > 0.f) ? o : expm1f(o);  // ELU
        out[(size_t)n * CD + tid] = o;
    }
}

// ---------------- launcher ----------------
extern "C" void kernel_launch(void* const* d_in, const int* in_sizes, int n_in,
                              void* d_out, int out_size)
{
    const float* x = (const float*)d_in[0];
    const int* ei = (const int*)d_in[1];
    const float* ea = (const float*)d_in[2];
    const float *Wl[3], *bl[3], *We[3], *att[3], *bb[3];
    for (int l = 0; l < 3; l++) {
        Wl[l]  = (const float*)d_in[3 + l * 5 + 0];
        bl[l]  = (const float*)d_in[3 + l * 5 + 1];
        We[l]  = (const float*)d_in[3 + l * 5 + 2];
        att[l] = (const float*)d_in[3 + l * 5 + 3];
        bb[l]  = (const float*)d_in[3 + l * 5 + 4];
    }
    float* out = (float*)d_out;

    float *p_xl, *p_h1, *p_h2;
    cudaGetSymbolAddress((void**)&p_xl, g_xl);
    cudaGetSymbolAddress((void**)&p_h1, g_h1);
    cudaGetSymbolAddress((void**)&p_h2, g_h2);

    dim3 gg((NN + BM - 1) / BM, HC / BN);

    k_gemm<<<gg, 256>>>(x, Wl[0], bl[0], p_xl, 128);     // 0: layer-0 GEMM
    k_degscan<<<1, 1024>>>(ei);                          // 1
    k_scatter2<<<(NE + 255) / 256, 256>>>(ei, ea);       // 2
    k_gat<<<NN, 160>>>(We[0], att[0], bb[0], p_h1);      // 3  (profiled slot)
    k_gemm<<<gg, 256>>>(p_h1, Wl[1], bl[1], p_xl, 64);   // 4
    k_gat<<<NN, 160>>>(We[1], att[1], bb[1], p_h2);      // 5
    k_gemm<<<gg, 256>>>(p_h2, Wl[2], bl[2], p_xl, 64);   // 6
    k_gat<<<NN, 160>>>(We[2], att[2], bb[2], out);       // 7
}

// round 11
// speedup vs baseline: 1.7240x; 1.7240x over previous
#include <cuda_runtime.h>
#include <math.h>

#define NN 10000
#define NE 200000
#define HC 320          // HEADS*CONV_DIM = 5*64
#define CD 64
#define ED 16

typedef unsigned long long u64;

// ---------------- device scratch (no allocations allowed) ----------------
__device__ __align__(16) float g_xl[NN * HC];         // per-layer node features [N,320]
__device__ __align__(16) float g_h1[NN * CD];
__device__ __align__(16) float g_h2[NN * CD];
__device__ __align__(16) float g_ea2[(NE + 32) * ED]; // edge_attr permuted to CSR order (+pad)
__device__ __align__(16) int g_srcs[NE + 32];         // src node per CSR slot (+pad)
__device__ int g_off[NN + 1];                         // CSR offsets (by dst)
__device__ int g_cnt[NN];

// ---------------- f32x2 / async helpers ----------------
__device__ __forceinline__ u64 pk2(float lo, float hi) {
    u64 r;
    asm("mov.b64 %0, {%1, %2};" : "=l"(r) : "f"(lo), "f"(hi));
    return r;
}
__device__ __forceinline__ void upk2(u64 v, float& lo, float& hi) {
    asm("mov.b64 {%0, %1}, %2;" : "=f"(lo), "=f"(hi) : "l"(v));
}
__device__ __forceinline__ u64 ffma2(u64 a, u64 b, u64 c) {
    u64 d;
    asm("fma.rn.f32x2 %0, %1, %2, %3;" : "=l"(d) : "l"(a), "l"(b), "l"(c));
    return d;
}
__device__ __forceinline__ u64 fadd2(u64 a, u64 b) {
    u64 d;
    asm("add.rn.f32x2 %0, %1, %2;" : "=l"(d) : "l"(a), "l"(b));
    return d;
}
__device__ __forceinline__ u64 fmul2(u64 a, u64 b) {
    u64 d;
    asm("mul.rn.f32x2 %0, %1, %2;" : "=l"(d) : "l"(a), "l"(b));
    return d;
}
__device__ __forceinline__ float ex2f(float x) {
    float r;
    asm("ex2.approx.f32 %0, %1;" : "=f"(r) : "f"(x));
    return r;
}
__device__ __forceinline__ void cp16(void* smem_dst, const void* gmem_src) {
    unsigned s = (unsigned)__cvta_generic_to_shared(smem_dst);
    asm volatile("cp.async.cg.shared.global [%0], [%1], 16;" :: "r"(s), "l"(gmem_src));
}
__device__ __forceinline__ void cp4(void* smem_dst, const void* gmem_src) {
    unsigned s = (unsigned)__cvta_generic_to_shared(smem_dst);
    asm volatile("cp.async.ca.shared.global [%0], [%1], 4;" :: "r"(s), "l"(gmem_src));
}
__device__ __forceinline__ void cp_commit() {
    asm volatile("cp.async.commit_group;");
}
__device__ __forceinline__ void cp_wait0() {
    asm volatile("cp.async.wait_group 0;");
}

// ---------------- preprocessing ----------------
// One block: histogram degrees in smem, scan, write offsets + zero counters.
__global__ void __launch_bounds__(1024) k_degscan(const int* __restrict__ ei) {
    __shared__ int hist[NN];
    __shared__ int sums[1024];
    const int t = threadIdx.x;
    for (int i = t; i < NN; i += 1024) hist[i] = 0;
    __syncthreads();
    for (int e = t; e < NE; e += 1024) atomicAdd(&hist[ei[NE + e]], 1);
    __syncthreads();
    const int per = 10;  // 1024*10 >= 10000
    int base = t * per;
    int s = 0;
#pragma unroll
    for (int i = 0; i < per; i++) {
        int idx = base + i;
        if (idx < NN) s += hist[idx];
    }
    sums[t] = s;
    __syncthreads();
    for (int off = 1; off < 1024; off <<= 1) {
        int v = 0;
        if (t >= off) v = sums[t - off];
        __syncthreads();
        sums[t] += v;
        __syncthreads();
    }
    int run = (t == 0) ? 0 : sums[t - 1];
#pragma unroll
    for (int i = 0; i < per; i++) {
        int idx = base + i;
        if (idx < NN) {
            g_off[idx] = run;
            g_cnt[idx] = 0;
            run += hist[idx];
        }
    }
    if (t == 0) g_off[NN] = NE;
}

// Scatter edges into CSR order: src ids + permuted edge_attr rows in one pass.
__global__ void k_scatter2(const int* __restrict__ ei, const float* __restrict__ ea) {
    int e = blockIdx.x * blockDim.x + threadIdx.x;
    if (e >= NE) return;
    int d = ei[NE + e];
    int pos = g_off[d] + atomicAdd(&g_cnt[d], 1);
    g_srcs[pos] = ei[e];
    const float4* r = (const float4*)(ea + (size_t)e * ED);
    float4 v0 = r[0], v1 = r[1], v2 = r[2], v3 = r[3];
    float4* w = (float4*)(g_ea2 + (size_t)pos * ED);
    w[0] = v0; w[1] = v1; w[2] = v2; w[3] = v3;
}

// ---------------- GEMM: C[M,320] = A[M,K] @ W[K,320] + bias ----------------
#define BM 128
#define BN 64
#define BK 16

__global__ void __launch_bounds__(256) k_gemm(
    const float* __restrict__ A, const float* __restrict__ W,
    const float* __restrict__ bias, float* __restrict__ C, int K)
{
    __shared__ float At[BK][BM + 4];
    __shared__ float Bs[BK][BN];
    const int tid = threadIdx.x;
    const int row0 = blockIdx.x * BM;
    const int col0 = blockIdx.y * BN;
    const int tx = tid & 15;
    const int ty = tid >> 4;

    float acc[8][4];
#pragma unroll
    for (int i = 0; i < 8; i++)
#pragma unroll
        for (int j = 0; j < 4; j++) acc[i][j] = 0.f;

    for (int k0 = 0; k0 < K; k0 += BK) {
#pragma unroll
        for (int i = 0; i < 2; i++) {
            int f = tid * 2 + i;
            int r = f >> 2;
            int kc = (f & 3) << 2;
            int gr = row0 + r;
            float4 v = make_float4(0.f, 0.f, 0.f, 0.f);
            if (gr < NN) v = *(const float4*)(A + (size_t)gr * K + k0 + kc);
            At[kc + 0][r] = v.x;
            At[kc + 1][r] = v.y;
            At[kc + 2][r] = v.z;
            At[kc + 3][r] = v.w;
        }
        {
            int k = tid >> 4;
            int c = (tid & 15) << 2;
            *(float4*)&Bs[k][c] = *(const float4*)(W + (size_t)(k0 + k) * HC + col0 + c);
        }
        __syncthreads();
#pragma unroll
        for (int k = 0; k < BK; k++) {
            float a[8], b[4];
            *(float4*)&a[0] = *(const float4*)&At[k][ty * 8];
            *(float4*)&a[4] = *(const float4*)&At[k][ty * 8 + 4];
            *(float4*)&b[0] = *(const float4*)&Bs[k][tx * 4];
#pragma unroll
            for (int i = 0; i < 8; i++)
#pragma unroll
                for (int j = 0; j < 4; j++)
                    acc[i][j] = fmaf(a[i], b[j], acc[i][j]);
        }
        __syncthreads();
    }

    float4 bv = *(const float4*)&bias[col0 + tx * 4];
#pragma unroll
    for (int i = 0; i < 8; i++) {
        int gr = row0 + ty * 8 + i;
        if (gr < NN) {
            float4 o;
            o.x = acc[i][0] + bv.x;
            o.y = acc[i][1] + bv.y;
            o.z = acc[i][2] + bv.z;
            o.w = acc[i][3] + bv.w;
            *(float4*)&C[(size_t)gr * HC + col0 + tx * 4] = o;
        }
    }
}

// ---------------- fused GATv2 layer v10b ----------------
// 160 threads = 5 warps = 1 node; warp h owns head h (2 comps/lane, packed f32x2).
// cp.async double-buffered window staging (fire-and-forget, no LDG->STS regs;
// src ids via 4-byte cp.async since CSR offsets are only 4B-aligned),
// group-of-4 compute with gather prefetch, virtual self loop, exp2 softmax.
// 5 blocks/SM (81-reg cap) for latency hiding.
__global__ void __launch_bounds__(160, 5) k_gat(
    const float* __restrict__ We, const float* __restrict__ att,
    const float* __restrict__ bias, float* __restrict__ out)
{
    const int tid = threadIdx.x;
    const int lane = tid & 31;
    const int h = tid >> 5;
    const int coff = h * 64 + 2 * lane;
    const unsigned FULL = 0xffffffffu;
    const float LOG2E = 1.4426950408889634f;

    const float attx = att[coff] * LOG2E;
    const float atty = att[coff + 1] * LOG2E;
    u64 We2[16];
#pragma unroll
    for (int kk = 0; kk < 8; kk++) {
        We2[kk]     = pk2(We[(2 * kk) * HC + coff],     We[(2 * kk + 1) * HC + coff]);
        We2[kk + 8] = pk2(We[(2 * kk) * HC + coff + 1], We[(2 * kk + 1) * HC + coff + 1]);
    }
    const u64 C02 = pk2(0.2f, 0.2f);

    __shared__ float s_red[5][64];
    __shared__ __align__(16) u64 s_ea[2][32][8];   // 2 x 2KB windows
    __shared__ __align__(16) int s_src[2][32];

    const int n = blockIdx.x;
    const u64 xld2 = *(const u64*)(g_xl + (size_t)n * HC + coff);
    const int base0 = g_off[n];
    const int deg = g_off[n + 1] - base0;
    const int nwin = (deg + 31) >> 5;

    float den = 0.f;
    u64 acc2 = pk2(0.f, 0.f);
    u64 es0 = pk2(0.f, 0.f), es1 = pk2(0.f, 0.f);  // running e_emb sums (self loop)

    // stage window 0 (arrays are padded; full-window copies are always safe)
    if (nwin > 0) {
        if (tid < 128) {
            cp16(&((char*)s_ea[0])[tid * 16],
                 (const char*)(g_ea2 + (size_t)base0 * ED) + tid * 16);
        } else {
            cp4(&s_src[0][tid - 128], g_srcs + base0 + (tid - 128));
        }
        cp_commit();
    }

    for (int w = 0; w < nwin; w++) {
        const int buf = w & 1;
        cp_wait0();
        __syncthreads();   // window data visible to all; prior compute done

        // stage next window (overlapped with this window's compute)
        if (w + 1 < nwin) {
            const int gb = base0 + (w + 1) * 32;
            if (tid < 128) {
                cp16(&((char*)s_ea[buf ^ 1])[tid * 16],
                     (const char*)(g_ea2 + (size_t)gb * ED) + tid * 16);
            } else {
                cp4(&s_src[buf ^ 1][tid - 128], g_srcs + gb + (tid - 128));
            }
            cp_commit();
        }

        const int cnt = min(32, deg - w * 32);

        // preload gathers for group 0
        u64 xs2[4];
#pragma unroll
        for (int j = 0; j < 4; j++)
            xs2[j] = *(const u64*)(g_xl + (size_t)s_src[buf][min(j, cnt - 1)] * HC + coff);

        for (int g0 = 0; g0 < cnt; g0 += 4) {
            const int vcnt = min(4, cnt - g0);

            // consume xs2 immediately; registers become free for prefetch
            u64 xsum[4];
#pragma unroll
            for (int j = 0; j < 4; j++) xsum[j] = fadd2(xs2[j], xld2);

            // prefetch next group's gathers
            if (g0 + 4 < cnt) {
#pragma unroll
                for (int j = 0; j < 4; j++)
                    xs2[j] = *(const u64*)(g_xl +
                        (size_t)s_src[buf][min(g0 + 4 + j, cnt - 1)] * HC + coff);
            }

            float sc[4];
#pragma unroll
            for (int j = 0; j < 4; j++) {
                if (j < vcnt) {
                    const ulonglong2* q = (const ulonglong2*)s_ea[buf][g0 + j];
                    ulonglong2 q0 = q[0], q1 = q[1], q2 = q[2], q3 = q[3];
                    u64 a0 = pk2(0.f, 0.f), a1 = pk2(0.f, 0.f);
                    a0 = ffma2(q0.x, We2[0], a0);  a1 = ffma2(q0.x, We2[8],  a1);
                    a0 = ffma2(q0.y, We2[1], a0);  a1 = ffma2(q0.y, We2[9],  a1);
                    a0 = ffma2(q1.x, We2[2], a0);  a1 = ffma2(q1.x, We2[10], a1);
                    a0 = ffma2(q1.y, We2[3], a0);  a1 = ffma2(q1.y, We2[11], a1);
                    a0 = ffma2(q2.x, We2[4], a0);  a1 = ffma2(q2.x, We2[12], a1);
                    a0 = ffma2(q2.y, We2[5], a0);  a1 = ffma2(q2.y, We2[13], a1);
                    a0 = ffma2(q3.x, We2[6], a0);  a1 = ffma2(q3.x, We2[14], a1);
                    a0 = ffma2(q3.y, We2[7], a0);  a1 = ffma2(q3.y, We2[15], a1);
                    es0 = fadd2(es0, a0);          // e_emb running sums (self loop)
                    es1 = fadd2(es1, a1);
                    float l0, h0, l1, h1;
                    upk2(a0, l0, h0);
                    upk2(a1, l1, h1);
                    u64 upair = fadd2(pk2(l0 + h0, l1 + h1), xsum[j]);
                    u64 tpair = fmul2(upair, C02);
                    float u0, u1, t0, t1;
                    upk2(upair, u0, u1);
                    upk2(tpair, t0, t1);
                    float lr0 = fmaxf(u0, t0);
                    float lr1 = fmaxf(u1, t1);
                    sc[j] = fmaf(attx, lr0, atty * lr1);
                } else {
                    sc[j] = -1000.f;   // exp2 -> 0
                }
            }

            // 4 pipelined butterflies (identical sums on all lanes)
#pragma unroll
            for (int o = 16; o; o >>= 1) {
#pragma unroll
                for (int j = 0; j < 4; j++)
                    sc[j] += __shfl_xor_sync(FULL, sc[j], o);
            }

            // direct softmax accumulation over (xs + xld)
#pragma unroll
            for (int j = 0; j < 4; j++) {
                float p = ex2f(fminf(sc[j], 100.f));
                den += p;
                acc2 = ffma2(pk2(p, p), xsum[j], acc2);
            }
        }
        __syncthreads();   // all warps done with buf before it is restaged
    }

    // undo the +xld aggregation bias: acc_true = acc - den*xld
    acc2 = ffma2(pk2(-den, -den), xld2, acc2);

    // virtual self loop: e_emb = mean of edge e_embs; x-part = 2*xld
    {
        float inv = (deg > 0) ? (1.f / (float)deg) : 1.f;
        float e0l, e0h, e1l, e1h, xx, xy;
        upk2(es0, e0l, e0h);
        upk2(es1, e1l, e1h);
        upk2(xld2, xx, xy);
        float u0 = fmaf(e0l + e0h, inv, 2.f * xx);
        float u1 = fmaf(e1l + e1h, inv, 2.f * xy);
        float lr0 = fmaxf(u0, 0.2f * u0);
        float lr1 = fmaxf(u1, 0.2f * u1);
        float scl = fmaf(attx, lr0, atty * lr1);
#pragma unroll
        for (int o = 16; o; o >>= 1) scl += __shfl_xor_sync(FULL, scl, o);
        float p = ex2f(fminf(scl, 100.f));
        den += p;
        acc2 = ffma2(pk2(p, p), xld2, acc2);
    }

    float invd = 1.f / den;
    float acc0, acc1;
    upk2(acc2, acc0, acc1);
    s_red[h][2 * lane]     = acc0 * invd;
    s_red[h][2 * lane + 1] = acc1 * invd;
    __syncthreads();

    if (tid < CD) {
        float o = (s_red[0][tid] + s_red[1][tid] + s_red[2][tid] +
                   s_red[3][tid] + s_red[4][tid]) * 0.2f + bias[tid];
        o = (o > 0.f) ? o : expm1f(o);  // ELU
        out[(size_t)n * CD + tid] = o;
    }
}

// ---------------- launcher ----------------
extern "C" void kernel_launch(void* const* d_in, const int* in_sizes, int n_in,
                              void* d_out, int out_size)
{
    const float* x = (const float*)d_in[0];
    const int* ei = (const int*)d_in[1];
    const float* ea = (const float*)d_in[2];
    const float *Wl[3], *bl[3], *We[3], *att[3], *bb[3];
    for (int l = 0; l < 3; l++) {
        Wl[l]  = (const float*)d_in[3 + l * 5 + 0];
        bl[l]  = (const float*)d_in[3 + l * 5 + 1];
        We[l]  = (const float*)d_in[3 + l * 5 + 2];
        att[l] = (const float*)d_in[3 + l * 5 + 3];
        bb[l]  = (const float*)d_in[3 + l * 5 + 4];
    }
    float* out = (float*)d_out;

    float *p_xl, *p_h1, *p_h2;
    cudaGetSymbolAddress((void**)&p_xl, g_xl);
    cudaGetSymbolAddress((void**)&p_h1, g_h1);
    cudaGetSymbolAddress((void**)&p_h2, g_h2);

    dim3 gg((NN + BM - 1) / BM, HC / BN);

    k_gemm<<<gg, 256>>>(x, Wl[0], bl[0], p_xl, 128);     // 0: layer-0 GEMM
    k_degscan<<<1, 1024>>>(ei);                          // 1
    k_scatter2<<<(NE + 255) / 256, 256>>>(ei, ea);       // 2
    k_gat<<<NN, 160>>>(We[0], att[0], bb[0], p_h1);      // 3
    k_gemm<<<gg, 256>>>(p_h1, Wl[1], bl[1], p_xl, 64);   // 4
    k_gat<<<NN, 160>>>(We[1], att[1], bb[1], p_h2);      // 5 (profiled slot)
    k_gemm<<<gg, 256>>>(p_h2, Wl[2], bl[2], p_xl, 64);   // 6
    k_gat<<<NN, 160>>>(We[2], att[2], bb[2], out);       // 7
}